// round 10
// baseline (speedup 1.0000x reference)
#include <cuda_runtime.h>
#include <cuda_bf16.h>
#include <cstdint>

#define T_TOK 16384
#define HDIM  2048
typedef __nv_bfloat16 bf16;

// ---------------- static device scratch ----------------
__device__ bf16  g_xhi[(size_t)T_TOK * HDIM];
__device__ bf16  g_xlo[(size_t)T_TOK * HDIM];
__device__ float g_combined[(size_t)T_TOK * HDIM];
__device__ bf16  g_chi[(size_t)T_TOK * HDIM];
__device__ bf16  g_clo[(size_t)T_TOK * HDIM];
__device__ float g_hmid[(size_t)T_TOK * 512];
__device__ bf16  g_mAhi[(size_t)T_TOK * 1024];
__device__ bf16  g_mAlo[(size_t)T_TOK * 1024];
__device__ bf16  g_mBhi[(size_t)T_TOK * 1024];
__device__ bf16  g_mBlo[(size_t)T_TOK * 1024];
// transposed+split weights pool [N][K] layout
#define O_SELW1 0u
#define O_C1 1048576u
#define O_F1 3145728u
#define O_D1 4194304u
#define O_C2 6291456u
#define O_F2 7340032u
#define O_D2 7602176u
#define W_POOL 8650752u
__device__ bf16 g_whi[W_POOL];
__device__ bf16 g_wlo[W_POOL];
__device__ int g_sel[T_TOK];
__device__ int g_idx1[T_TOK];
__device__ int g_idx2[T_TOK];
__device__ int g_fix[T_TOK];
__device__ int g_cnt[4];   // [0]=cnt1 [1]=cnt2 [2]=nfix

// ---------------- helpers ----------------
__device__ __forceinline__ uint32_t smem_u32(const void* p) {
    uint32_t a;
    asm("{ .reg .u64 t; cvta.to.shared.u64 t, %1; cvt.u32.u64 %0, t; }" : "=r"(a) : "l"(p));
    return a;
}
__device__ __forceinline__ void cp16(uint32_t dst, const void* src) {
    asm volatile("cp.async.cg.shared.global [%0], [%1], 16;" :: "r"(dst), "l"(src));
}
#define CP_COMMIT() asm volatile("cp.async.commit_group;" ::: "memory")
#define CP_WAIT1()  asm volatile("cp.async.wait_group 1;" ::: "memory")
#define CP_WAIT0()  asm volatile("cp.async.wait_group 0;" ::: "memory")

__device__ __forceinline__ void ldmx4(uint32_t* r, uint32_t addr) {
    asm volatile("ldmatrix.sync.aligned.m8n8.x4.shared.b16 {%0,%1,%2,%3}, [%4];"
        : "=r"(r[0]), "=r"(r[1]), "=r"(r[2]), "=r"(r[3]) : "r"(addr));
}
__device__ __forceinline__ void mma_bf16(float* c, const uint32_t* a, uint32_t b0, uint32_t b1) {
    asm volatile("mma.sync.aligned.m16n8k16.row.col.f32.bf16.bf16.f32 "
        "{%0,%1,%2,%3}, {%4,%5,%6,%7}, {%8,%9}, {%0,%1,%2,%3};"
        : "+f"(c[0]), "+f"(c[1]), "+f"(c[2]), "+f"(c[3])
        : "r"(a[0]), "r"(a[1]), "r"(a[2]), "r"(a[3]), "r"(b0), "r"(b1));
}
__device__ __forceinline__ void split2(float v, bf16& h, bf16& l) {
    h = __float2bfloat16_rn(v);
    l = __float2bfloat16_rn(v - __bfloat162float(h));
}

// ---------------- prep: split x, build combined + split ----------------
__global__ void prep_kernel(const float* __restrict__ x, const float* __restrict__ freq,
                            const float* __restrict__ imp) {
    size_t i4 = (size_t)blockIdx.x * blockDim.x + threadIdx.x;
    size_t e = i4 * 4;
    if (e >= (size_t)T_TOK * HDIM) return;
    int t = (int)(e / HDIM);
    int h = (int)(e % HDIM);
    float s = (h < 1024) ? freq[t] : imp[t];
    float4 v = *(const float4*)(x + e);
    float c0 = v.x * s, c1 = v.y * s, c2 = v.z * s, c3 = v.w * s;
    bf16 xh[4], xl[4], ch[4], cl[4];
    split2(v.x, xh[0], xl[0]); split2(v.y, xh[1], xl[1]);
    split2(v.z, xh[2], xl[2]); split2(v.w, xh[3], xl[3]);
    split2(c0, ch[0], cl[0]); split2(c1, ch[1], cl[1]);
    split2(c2, ch[2], cl[2]); split2(c3, ch[3], cl[3]);
    *(uint2*)(g_xhi + e) = *(uint2*)xh;
    *(uint2*)(g_xlo + e) = *(uint2*)xl;
    *(uint2*)(g_chi + e) = *(uint2*)ch;
    *(uint2*)(g_clo + e) = *(uint2*)cl;
    float4 cv; cv.x = c0; cv.y = c1; cv.z = c2; cv.w = c3;
    *(float4*)(g_combined + e) = cv;
}

// ---------------- weight transpose + split: W[K][N] -> Wt[N][K] hi/lo ----------------
__global__ void transpose_split_kernel(const float* __restrict__ W, int K, int N,
                                       bf16* __restrict__ hi, bf16* __restrict__ lo) {
    __shared__ float tile[32][33];
    int nb = blockIdx.x * 32, kb = blockIdx.y * 32;
#pragma unroll
    for (int r = 0; r < 4; r++) {
        int k = kb + threadIdx.y + r * 8;
        tile[threadIdx.y + r * 8][threadIdx.x] = W[(size_t)k * N + nb + threadIdx.x];
    }
    __syncthreads();
#pragma unroll
    for (int r = 0; r < 4; r++) {
        int n = nb + threadIdx.y + r * 8;
        int k = kb + threadIdx.x;
        float v = tile[threadIdx.x][threadIdx.y + r * 8];
        bf16 h, l; split2(v, h, l);
        hi[(size_t)n * K + k] = h;
        lo[(size_t)n * K + k] = l;
    }
}

__global__ void init_counters_kernel() { g_cnt[0] = 0; g_cnt[1] = 0; g_cnt[2] = 0; }

// ---------------- mma.sync split-bf16 GEMM ----------------
// CTA tile 128x64, 4 warps each 64x32 (2x2). BK=64 (128B rows, SW128 swizzle).
// cp.async double buffer, 3-term split. 96KB smem -> 2 CTAs/SM.
#define STAGE_BYTES 49152
#define OFF_AH 0
#define OFF_AL 16384
#define OFF_BH 32768
#define OFF_BL 40960
#define GEMM_SMEM (2 * STAGE_BYTES)

__global__ __launch_bounds__(128, 2)
void gemm_mma(const bf16* __restrict__ Ahi, const bf16* __restrict__ Alo, int ldA,
              const bf16* __restrict__ Bhi, const bf16* __restrict__ Blo, int ldB,
              const float* __restrict__ bias, int Kfull,
              float* __restrict__ Cf, int ldCf,
              bf16* __restrict__ Chi, bf16* __restrict__ Clo, int ldCb,
              const int* __restrict__ gather, const int* __restrict__ scatter,
              const int* __restrict__ cnt, int Mfix, int relu) {
    extern __shared__ char sm[];
    int count = cnt ? *cnt : Mfix;
    int m0 = blockIdx.y * 128;
    if (m0 >= count) return;
    int n0 = blockIdx.x * 64;
    uint32_t smb = smem_u32(sm);
    int tid = threadIdx.x, wid = tid >> 5, lane = tid & 31;

    // ---- gmem->smem mapping
    // A: one full 128B row per thread (rows 0..127), 8 x 16B segments, hi+lo
    uint32_t swA[8];
#pragma unroll
    for (int i = 0; i < 8; i++) {
        uint32_t bo = (uint32_t)tid * 128 + i * 16;
        swA[i] = bo ^ ((bo >> 3) & 0x70);
    }
    int ar = m0 + tid; if (ar > count - 1) ar = count - 1;
    int ag = gather ? gather[ar] : ar;
    const bf16* pah = Ahi + (size_t)ag * ldA;
    const bf16* pal = Alo + (size_t)ag * ldA;
    // B: row = tid>>1 (0..63), half = tid&1 (two 64B halves), hi+lo
    int brow = tid >> 1, bhalf = tid & 1;
    uint32_t swB[4];
#pragma unroll
    for (int i = 0; i < 4; i++) {
        uint32_t bo = (uint32_t)brow * 128 + bhalf * 64 + i * 16;
        swB[i] = bo ^ ((bo >> 3) & 0x70);
    }
    const bf16* pbh = Bhi + (size_t)(n0 + brow) * ldB + bhalf * 32;
    const bf16* pbl = Blo + (size_t)(n0 + brow) * ldB + bhalf * 32;

    int nch = Kfull >> 6;

    // ---- compute mapping: 4 warps = 2 m-rows x 2 n-cols, each 64x32
    int wr = wid >> 1, wc = wid & 1;
    int m_base = wr * 64, n_base = wc * 32;

    float acc[4][4][4];
#pragma unroll
    for (int a = 0; a < 4; a++)
#pragma unroll
        for (int b = 0; b < 4; b++)
#pragma unroll
            for (int c = 0; c < 4; c++) acc[a][b][c] = 0.f;

    // prologue: chunk 0 -> stage 0
    {
        uint32_t st = smb;
#pragma unroll
        for (int i = 0; i < 8; i++) {
            cp16(st + OFF_AH + swA[i], pah + i * 8);
            cp16(st + OFF_AL + swA[i], pal + i * 8);
        }
#pragma unroll
        for (int i = 0; i < 4; i++) {
            cp16(st + OFF_BH + swB[i], pbh + i * 8);
            cp16(st + OFF_BL + swB[i], pbl + i * 8);
        }
    }
    CP_COMMIT();

    for (int c = 0; c < nch; c++) {
        if (c + 1 < nch) {
            uint32_t st = smb + ((c + 1) & 1) * STAGE_BYTES;
            int ke = (c + 1) * 64;
#pragma unroll
            for (int i = 0; i < 8; i++) {
                cp16(st + OFF_AH + swA[i], pah + ke + i * 8);
                cp16(st + OFF_AL + swA[i], pal + ke + i * 8);
            }
#pragma unroll
            for (int i = 0; i < 4; i++) {
                cp16(st + OFF_BH + swB[i], pbh + ke + i * 8);
                cp16(st + OFF_BL + swB[i], pbl + ke + i * 8);
            }
            CP_COMMIT();
            CP_WAIT1();
        } else {
            CP_WAIT0();
        }
        __syncthreads();

        uint32_t sb = smb + (c & 1) * STAGE_BYTES;
#pragma unroll
        for (int kk = 0; kk < 4; kk++) {
            // B fragments: 4 n8-tiles via 2x ldmatrix.x4 (hi and lo)
            uint32_t brw = n_base + ((lane & 7) | ((lane >> 1) & 8));
            uint32_t bkb = kk * 32 + ((lane >> 3) & 1) * 16;
            uint32_t bh[8], bl[8];
#pragma unroll
            for (int np = 0; np < 2; np++) {
                uint32_t bo = (brw + np * 16) * 128 + bkb;
                uint32_t ad = sb + (bo ^ ((bo >> 3) & 0x70));
                ldmx4(bh + np * 4, ad + OFF_BH);
                ldmx4(bl + np * 4, ad + OFF_BL);
            }
            uint32_t arw = m_base + (lane & 15);
            uint32_t akb = kk * 32 + ((lane >> 4) & 1) * 16;
#pragma unroll
            for (int mt = 0; mt < 4; mt++) {
                uint32_t bo = (arw + mt * 16) * 128 + akb;
                uint32_t ad = sb + (bo ^ ((bo >> 3) & 0x70));
                uint32_t ah[4], al[4];
                ldmx4(ah, ad + OFF_AH);
                ldmx4(al, ad + OFF_AL);
#pragma unroll
                for (int nt = 0; nt < 4; nt++) {
                    int bi = (nt >> 1) * 4 + (nt & 1) * 2;
                    mma_bf16(acc[mt][nt], ah, bh[bi], bh[bi + 1]);
                    mma_bf16(acc[mt][nt], ah, bl[bi], bl[bi + 1]);
                    mma_bf16(acc[mt][nt], al, bh[bi], bh[bi + 1]);
                }
            }
        }
        __syncthreads();
    }

    // ---- epilogue: bias (+relu), direct stores
#pragma unroll
    for (int mt = 0; mt < 4; mt++) {
#pragma unroll
        for (int h2 = 0; h2 < 2; h2++) {
            int r = m0 + m_base + mt * 16 + h2 * 8 + (lane >> 2);
            if (r >= count) continue;
            int orow = scatter ? scatter[r] : r;
#pragma unroll
            for (int nt = 0; nt < 4; nt++) {
                int col = n0 + n_base + nt * 8 + (lane & 3) * 2;
                float v0 = acc[mt][nt][h2 * 2 + 0] + bias[col];
                float v1 = acc[mt][nt][h2 * 2 + 1] + bias[col + 1];
                if (relu) { v0 = fmaxf(v0, 0.f); v1 = fmaxf(v1, 0.f); }
                if (Cf) {
                    float2 o; o.x = v0; o.y = v1;
                    *(float2*)(Cf + (size_t)orow * ldCf + col) = o;
                }
                if (Chi) {
                    bf16 h0, l0, h1, l1;
                    split2(v0, h0, l0); split2(v1, h1, l1);
                    size_t co = (size_t)r * ldCb + col;
                    __nv_bfloat162 ph; ph.x = h0; ph.y = h1;
                    __nv_bfloat162 pl; pl.x = l0; pl.y = l1;
                    *(__nv_bfloat162*)(Chi + co) = ph;
                    *(__nv_bfloat162*)(Clo + co) = pl;
                }
            }
        }
    }
}

// ---------------- logits + provisional argmax + ambiguity flag ----------------
__global__ void logits_kernel(const float* __restrict__ W2, const float* __restrict__ b2) {
    int warp = (blockIdx.x * blockDim.x + threadIdx.x) >> 5;
    int lane = threadIdx.x & 31;
    if (warp >= T_TOK) return;
    const float* hrow = g_hmid + (size_t)warp * 512;
    float s0 = 0.f, s1 = 0.f, s2 = 0.f;
    for (int k = lane * 4; k < 512; k += 128) {
        float4 h = *(const float4*)(hrow + k);
        const float* w = W2 + k * 3;
        s0 += h.x * w[0] + h.y * w[3] + h.z * w[6] + h.w * w[9];
        s1 += h.x * w[1] + h.y * w[4] + h.z * w[7] + h.w * w[10];
        s2 += h.x * w[2] + h.y * w[5] + h.z * w[8] + h.w * w[11];
    }
#pragma unroll
    for (int o = 16; o > 0; o >>= 1) {
        s0 += __shfl_xor_sync(0xffffffffu, s0, o);
        s1 += __shfl_xor_sync(0xffffffffu, s1, o);
        s2 += __shfl_xor_sync(0xffffffffu, s2, o);
    }
    if (lane == 0) {
        s0 += b2[0]; s1 += b2[1]; s2 += b2[2];
        int sel = 0; float best = s0;
        if (s1 > best) { best = s1; sel = 1; }
        if (s2 > best) { best = s2; sel = 2; }
        float second = (sel == 0) ? fmaxf(s1, s2) : (sel == 1 ? fmaxf(s0, s2) : fmaxf(s0, s1));
        g_sel[warp] = sel;
        if (best - second < 1e-3f) {
            int p = atomicAdd(&g_cnt[2], 1);
            g_fix[p] = warp;
        }
    }
}

// ---------------- fp32 exact recompute for ambiguous tokens ----------------
__global__ void fixup_kernel(const float* __restrict__ W1, const float* __restrict__ b1,
                             const float* __restrict__ W2, const float* __restrict__ b2) {
    __shared__ float hm[512];
    __shared__ float red[256];
    __shared__ float logit[3];
    int nfix = g_cnt[2];
    for (int i = blockIdx.x; i < nfix; i += gridDim.x) {
        int t = g_fix[i];
        const float* cr = g_combined + (size_t)t * HDIM;
        int j0 = threadIdx.x, j1 = threadIdx.x + 256;
        float a0 = b1[j0], a1 = b1[j1];
#pragma unroll 4
        for (int k = 0; k < HDIM; k++) {
            float c = __ldg(cr + k);
            a0 += c * W1[(size_t)k * 512 + j0];
            a1 += c * W1[(size_t)k * 512 + j1];
        }
        hm[j0] = fmaxf(a0, 0.f);
        hm[j1] = fmaxf(a1, 0.f);
        __syncthreads();
        for (int l = 0; l < 3; l++) {
            float p = hm[threadIdx.x] * W2[threadIdx.x * 3 + l] +
                      hm[threadIdx.x + 256] * W2[(threadIdx.x + 256) * 3 + l];
            red[threadIdx.x] = p; __syncthreads();
            for (int o = 128; o > 0; o >>= 1) {
                if (threadIdx.x < o) red[threadIdx.x] += red[threadIdx.x + o];
                __syncthreads();
            }
            if (threadIdx.x == 0) logit[l] = red[0] + b2[l];
            __syncthreads();
        }
        if (threadIdx.x == 0) {
            float s0 = logit[0], s1 = logit[1], s2 = logit[2];
            int sel = 0; float best = s0;
            if (s1 > best) { best = s1; sel = 1; }
            if (s2 > best) { sel = 2; }
            g_sel[t] = sel;
        }
        __syncthreads();
    }
}

__global__ void compact_kernel() {
    int t = blockIdx.x * blockDim.x + threadIdx.x;
    if (t >= T_TOK) return;
    int s = g_sel[t];
    if (s == 1)      { int p = atomicAdd(&g_cnt[0], 1); g_idx1[p] = t; }
    else if (s == 2) { int p = atomicAdd(&g_cnt[1], 1); g_idx2[p] = t; }
}

__global__ void copy0_kernel(const float* __restrict__ x, float* __restrict__ out) {
    int t = blockIdx.x;
    if (g_sel[t] != 0) return;
    const float4* src = (const float4*)(x + (size_t)t * HDIM);
    float4* dst = (float4*)(out + (size_t)t * HDIM);
    for (int i = threadIdx.x; i < HDIM / 4; i += blockDim.x) dst[i] = src[i];
}

// ---------------- launch ----------------
extern "C" void kernel_launch(void* const* d_in, const int* in_sizes, int n_in,
                              void* d_out, int out_size) {
    const float* x      = (const float*)d_in[0];
    const float* freq   = (const float*)d_in[1];
    const float* imp    = (const float*)d_in[2];
    const float* sel_W1 = (const float*)d_in[3];
    const float* sel_b1 = (const float*)d_in[4];
    const float* sel_W2 = (const float*)d_in[5];
    const float* sel_b2 = (const float*)d_in[6];
    const float* c1_W   = (const float*)d_in[7];
    const float* c1_b   = (const float*)d_in[8];
    const float* f1_W   = (const float*)d_in[9];
    const float* f1_b   = (const float*)d_in[10];
    const float* d1_W   = (const float*)d_in[11];
    const float* d1_b   = (const float*)d_in[12];
    const float* c2_W   = (const float*)d_in[13];
    const float* c2_b   = (const float*)d_in[14];
    const float* f2_W   = (const float*)d_in[15];
    const float* f2_b   = (const float*)d_in[16];
    const float* d2_W   = (const float*)d_in[17];
    const float* d2_b   = (const float*)d_in[18];
    float* out = (float*)d_out;

    bf16 *xhi, *xlo, *chi, *clo, *mAhi, *mAlo, *mBhi, *mBlo, *whi, *wlo;
    float *hmid;
    int *idx1, *idx2, *cnt;
    cudaGetSymbolAddress((void**)&xhi, g_xhi);
    cudaGetSymbolAddress((void**)&xlo, g_xlo);
    cudaGetSymbolAddress((void**)&chi, g_chi);
    cudaGetSymbolAddress((void**)&clo, g_clo);
    cudaGetSymbolAddress((void**)&mAhi, g_mAhi);
    cudaGetSymbolAddress((void**)&mAlo, g_mAlo);
    cudaGetSymbolAddress((void**)&mBhi, g_mBhi);
    cudaGetSymbolAddress((void**)&mBlo, g_mBlo);
    cudaGetSymbolAddress((void**)&whi, g_whi);
    cudaGetSymbolAddress((void**)&wlo, g_wlo);
    cudaGetSymbolAddress((void**)&hmid, g_hmid);
    cudaGetSymbolAddress((void**)&idx1, g_idx1);
    cudaGetSymbolAddress((void**)&idx2, g_idx2);
    cudaGetSymbolAddress((void**)&cnt, g_cnt);

    cudaFuncSetAttribute(gemm_mma, cudaFuncAttributeMaxDynamicSharedMemorySize, GEMM_SMEM);

    // 1) splits
    prep_kernel<<<(T_TOK * HDIM / 4 + 255) / 256, 256>>>(x, freq, imp);

    // 2) weight transpose + split  (grid: N/32 x K/32) — device pointers, not symbol shadows
    dim3 tb(32, 8);
    transpose_split_kernel<<<dim3(512 / 32, 2048 / 32), tb>>>(sel_W1, 2048, 512, whi + O_SELW1, wlo + O_SELW1);
    transpose_split_kernel<<<dim3(1024 / 32, 2048 / 32), tb>>>(c1_W, 2048, 1024, whi + O_C1, wlo + O_C1);
    transpose_split_kernel<<<dim3(1024 / 32, 1024 / 32), tb>>>(f1_W, 1024, 1024, whi + O_F1, wlo + O_F1);
    transpose_split_kernel<<<dim3(2048 / 32, 1024 / 32), tb>>>(d1_W, 1024, 2048, whi + O_D1, wlo + O_D1);
    transpose_split_kernel<<<dim3(512 / 32, 2048 / 32), tb>>>(c2_W, 2048, 512, whi + O_C2, wlo + O_C2);
    transpose_split_kernel<<<dim3(512 / 32, 512 / 32), tb>>>(f2_W, 512, 512, whi + O_F2, wlo + O_F2);
    transpose_split_kernel<<<dim3(2048 / 32, 512 / 32), tb>>>(d2_W, 512, 2048, whi + O_D2, wlo + O_D2);

    init_counters_kernel<<<1, 1>>>();

    const int MT = T_TOK / 128;   // 128 M-tiles (worst case)

    // 3) selector hidden (fp32 out, relu)
    gemm_mma<<<dim3(512 / 64, MT), 128, GEMM_SMEM>>>(
        chi, clo, 2048, whi + O_SELW1, wlo + O_SELW1, 2048, sel_b1, 2048,
        hmid, 512, nullptr, nullptr, 0, nullptr, nullptr, nullptr, T_TOK, 1);

    // 4) logits + argmax (+ ambiguity fixup) + compaction
    logits_kernel<<<T_TOK / 8, 256>>>(sel_W2, sel_b2);
    fixup_kernel<<<64, 256>>>(sel_W1, sel_b1, sel_W2, sel_b2);
    compact_kernel<<<T_TOK / 256, 256>>>();
    copy0_kernel<<<T_TOK, 128>>>(x, out);

    // 5) expert 1
    gemm_mma<<<dim3(1024 / 64, MT), 128, GEMM_SMEM>>>(
        xhi, xlo, 2048, whi + O_C1, wlo + O_C1, 2048, c1_b, 2048,
        nullptr, 0, mAhi, mAlo, 1024, idx1, nullptr, cnt + 0, 0, 0);
    gemm_mma<<<dim3(1024 / 64, MT), 128, GEMM_SMEM>>>(
        mAhi, mAlo, 1024, whi + O_F1, wlo + O_F1, 1024, f1_b, 1024,
        nullptr, 0, mBhi, mBlo, 1024, nullptr, nullptr, cnt + 0, 0, 0);
    gemm_mma<<<dim3(2048 / 64, MT), 128, GEMM_SMEM>>>(
        mBhi, mBlo, 1024, whi + O_D1, wlo + O_D1, 1024, d1_b, 1024,
        out, 2048, nullptr, nullptr, 0, nullptr, idx1, cnt + 0, 0, 0);

    // 6) expert 2
    gemm_mma<<<dim3(512 / 64, MT), 128, GEMM_SMEM>>>(
        xhi, xlo, 2048, whi + O_C2, wlo + O_C2, 2048, c2_b, 2048,
        nullptr, 0, mAhi, mAlo, 512, idx2, nullptr, cnt + 1, 0, 0);
    gemm_mma<<<dim3(512 / 64, MT), 128, GEMM_SMEM>>>(
        mAhi, mAlo, 512, whi + O_F2, wlo + O_F2, 512, f2_b, 512,
        nullptr, 0, mBhi, mBlo, 512, nullptr, nullptr, cnt + 1, 0, 0);
    gemm_mma<<<dim3(2048 / 64, MT), 128, GEMM_SMEM>>>(
        mBhi, mBlo, 512, whi + O_D2, wlo + O_D2, 512, d2_b, 512,
        out, 2048, nullptr, nullptr, 0, nullptr, idx2, cnt + 1, 0, 0);
}

// round 11
// speedup vs baseline: 1.1764x; 1.1764x over previous
#include <cuda_runtime.h>
#include <cuda_bf16.h>
#include <cstdint>

#define T_TOK 16384
#define HDIM  2048
typedef __nv_bfloat16 bf16;

// ---------------- static device scratch ----------------
__device__ bf16  g_xhi[(size_t)T_TOK * HDIM];
__device__ bf16  g_xlo[(size_t)T_TOK * HDIM];
__device__ float g_combined[(size_t)T_TOK * HDIM];
__device__ bf16  g_chi[(size_t)T_TOK * HDIM];
__device__ bf16  g_clo[(size_t)T_TOK * HDIM];
__device__ float g_hmid[(size_t)T_TOK * 512];
__device__ bf16  g_mAhi[(size_t)T_TOK * 1024];
__device__ bf16  g_mAlo[(size_t)T_TOK * 1024];
__device__ bf16  g_mBhi[(size_t)T_TOK * 1024];
__device__ bf16  g_mBlo[(size_t)T_TOK * 1024];
// transposed+split weights pool [N][K] layout
#define O_SELW1 0u
#define O_C1 1048576u
#define O_F1 3145728u
#define O_D1 4194304u
#define O_C2 6291456u
#define O_F2 7340032u
#define O_D2 7602176u
#define W_POOL 8650752u
__device__ bf16 g_whi[W_POOL];
__device__ bf16 g_wlo[W_POOL];
__device__ int g_sel[T_TOK];
__device__ int g_idx1[T_TOK];
__device__ int g_idx2[T_TOK];
__device__ int g_fix[T_TOK];
__device__ int g_cnt[4];   // [0]=cnt1 [1]=cnt2 [2]=nfix

// ---------------- helpers ----------------
__device__ __forceinline__ uint32_t smem_u32(const void* p) {
    uint32_t a;
    asm("{ .reg .u64 t; cvta.to.shared.u64 t, %1; cvt.u32.u64 %0, t; }" : "=r"(a) : "l"(p));
    return a;
}
__device__ __forceinline__ void cp16(uint32_t dst, const void* src) {
    asm volatile("cp.async.cg.shared.global [%0], [%1], 16;" :: "r"(dst), "l"(src));
}
#define CP_COMMIT() asm volatile("cp.async.commit_group;" ::: "memory")
#define CP_WAIT2()  asm volatile("cp.async.wait_group 2;" ::: "memory")
#define CP_WAIT1()  asm volatile("cp.async.wait_group 1;" ::: "memory")
#define CP_WAIT0()  asm volatile("cp.async.wait_group 0;" ::: "memory")

__device__ __forceinline__ void ldmx4(uint32_t* r, uint32_t addr) {
    asm volatile("ldmatrix.sync.aligned.m8n8.x4.shared.b16 {%0,%1,%2,%3}, [%4];"
        : "=r"(r[0]), "=r"(r[1]), "=r"(r[2]), "=r"(r[3]) : "r"(addr));
}
__device__ __forceinline__ void mma_bf16(float* c, const uint32_t* a, uint32_t b0, uint32_t b1) {
    asm volatile("mma.sync.aligned.m16n8k16.row.col.f32.bf16.bf16.f32 "
        "{%0,%1,%2,%3}, {%4,%5,%6,%7}, {%8,%9}, {%0,%1,%2,%3};"
        : "+f"(c[0]), "+f"(c[1]), "+f"(c[2]), "+f"(c[3])
        : "r"(a[0]), "r"(a[1]), "r"(a[2]), "r"(a[3]), "r"(b0), "r"(b1));
}
__device__ __forceinline__ void split2(float v, bf16& h, bf16& l) {
    h = __float2bfloat16_rn(v);
    l = __float2bfloat16_rn(v - __bfloat162float(h));
}

// ---------------- prep: split x, build combined + split, init counters ----------------
__global__ void prep_kernel(const float* __restrict__ x, const float* __restrict__ freq,
                            const float* __restrict__ imp) {
    if (blockIdx.x == 0 && threadIdx.x == 0) { g_cnt[0] = 0; g_cnt[1] = 0; g_cnt[2] = 0; }
    size_t i4 = (size_t)blockIdx.x * blockDim.x + threadIdx.x;
    size_t e = i4 * 4;
    if (e >= (size_t)T_TOK * HDIM) return;
    int t = (int)(e / HDIM);
    int h = (int)(e % HDIM);
    float s = (h < 1024) ? freq[t] : imp[t];
    float4 v = *(const float4*)(x + e);
    float c0 = v.x * s, c1 = v.y * s, c2 = v.z * s, c3 = v.w * s;
    bf16 xh[4], xl[4], ch[4], cl[4];
    split2(v.x, xh[0], xl[0]); split2(v.y, xh[1], xl[1]);
    split2(v.z, xh[2], xl[2]); split2(v.w, xh[3], xl[3]);
    split2(c0, ch[0], cl[0]); split2(c1, ch[1], cl[1]);
    split2(c2, ch[2], cl[2]); split2(c3, ch[3], cl[3]);
    *(uint2*)(g_xhi + e) = *(uint2*)xh;
    *(uint2*)(g_xlo + e) = *(uint2*)xl;
    *(uint2*)(g_chi + e) = *(uint2*)ch;
    *(uint2*)(g_clo + e) = *(uint2*)cl;
    float4 cv; cv.x = c0; cv.y = c1; cv.z = c2; cv.w = c3;
    *(float4*)(g_combined + e) = cv;
}

// ---------------- merged weight transpose + split (single launch) ----------------
struct WDesc { const float* src; int K; int N; unsigned off; int tile_start; };
struct WAll  { WDesc d[7]; };

__global__ void transpose_all_kernel(WAll wa) {
    __shared__ float tile[32][33];
    int bt = blockIdx.x;
    // find matrix: linear scan over 7 descriptors (tile_start ascending)
    int mi = 0;
#pragma unroll
    for (int i = 1; i < 7; i++) if (bt >= wa.d[i].tile_start) mi = i;
    const WDesc& d = wa.d[mi];
    int lt = bt - d.tile_start;
    int ntiles_n = d.N / 32;
    int nb = (lt % ntiles_n) * 32;
    int kb = (lt / ntiles_n) * 32;
    bf16* hi = g_whi + d.off;
    bf16* lo = g_wlo + d.off;
#pragma unroll
    for (int r = 0; r < 4; r++) {
        int k = kb + threadIdx.y + r * 8;
        tile[threadIdx.y + r * 8][threadIdx.x] = d.src[(size_t)k * d.N + nb + threadIdx.x];
    }
    __syncthreads();
#pragma unroll
    for (int r = 0; r < 4; r++) {
        int n = nb + threadIdx.y + r * 8;
        int k = kb + threadIdx.x;
        float v = tile[threadIdx.x][threadIdx.y + r * 8];
        bf16 h, l; split2(v, h, l);
        hi[(size_t)n * d.K + k] = h;
        lo[(size_t)n * d.K + k] = l;
    }
}

// ---------------- mma.sync split-bf16 GEMM (R8 config + 3-stage ring) ----------------
// CTA tile 128x128, 8 warps each 64x32. BK=64 (128B rows, SW128 swizzle).
#define STAGE_BYTES 65536
#define OFF_AH 0
#define OFF_AL 16384
#define OFF_BH 32768
#define OFF_BL 49152
#define GEMM_SMEM (3 * STAGE_BYTES)

__global__ __launch_bounds__(256, 1)
void gemm_mma(const bf16* __restrict__ Ahi, const bf16* __restrict__ Alo, int ldA,
              const bf16* __restrict__ Bhi, const bf16* __restrict__ Blo, int ldB,
              const float* __restrict__ bias, int Kfull,
              float* __restrict__ Cf, int ldCf,
              bf16* __restrict__ Chi, bf16* __restrict__ Clo, int ldCb,
              const int* __restrict__ gather, const int* __restrict__ scatter,
              const int* __restrict__ cnt, int Mfix, int relu) {
    extern __shared__ char sm[];
    int count = cnt ? *cnt : Mfix;
    int m0 = blockIdx.y * 128;
    if (m0 >= count) return;
    int n0 = blockIdx.x * 128;
    uint32_t smb = smem_u32(sm);
    int tid = threadIdx.x, wid = tid >> 5, lane = tid & 31;

    // ---- gmem->smem mapping: row = tid>>1 (0..127), half = tid&1
    int row = tid >> 1, half = tid & 1;
    uint32_t swoff[4];
#pragma unroll
    for (int i = 0; i < 4; i++) {
        uint32_t bo = (uint32_t)row * 128 + half * 64 + i * 16;
        swoff[i] = bo ^ ((bo >> 3) & 0x70);
    }
    int ar = m0 + row; if (ar > count - 1) ar = count - 1;
    int ag = gather ? gather[ar] : ar;
    const bf16* pah = Ahi + (size_t)ag * ldA + half * 32;
    const bf16* pal = Alo + (size_t)ag * ldA + half * 32;
    const bf16* pbh = Bhi + (size_t)(n0 + row) * ldB + half * 32;
    const bf16* pbl = Blo + (size_t)(n0 + row) * ldB + half * 32;

    int nch = Kfull >> 6;

    // ---- compute mapping: 8 warps = 2 m-rows x 4 n-cols, each 64x32
    int wr = wid >> 2, wc = wid & 3;
    int m_base = wr * 64, n_base = wc * 32;

    float acc[4][4][4];
#pragma unroll
    for (int a = 0; a < 4; a++)
#pragma unroll
        for (int b = 0; b < 4; b++)
#pragma unroll
            for (int c = 0; c < 4; c++) acc[a][b][c] = 0.f;

    // prologue: chunks 0,1 -> stages 0,1
#pragma unroll
    for (int p = 0; p < 2; p++) {
        uint32_t st = smb + p * STAGE_BYTES;
        int ke = p * 64;
#pragma unroll
        for (int i = 0; i < 4; i++) {
            cp16(st + OFF_AH + swoff[i], pah + ke + i * 8);
            cp16(st + OFF_AL + swoff[i], pal + ke + i * 8);
            cp16(st + OFF_BH + swoff[i], pbh + ke + i * 8);
            cp16(st + OFF_BL + swoff[i], pbl + ke + i * 8);
        }
        CP_COMMIT();
    }

    int stage = 0;
    for (int c = 0; c < nch; c++) {
        if (c + 2 < nch) {
            int ws = (c + 2) % 3;
            uint32_t st = smb + ws * STAGE_BYTES;
            int ke = (c + 2) * 64;
#pragma unroll
            for (int i = 0; i < 4; i++) {
                cp16(st + OFF_AH + swoff[i], pah + ke + i * 8);
                cp16(st + OFF_AL + swoff[i], pal + ke + i * 8);
                cp16(st + OFF_BH + swoff[i], pbh + ke + i * 8);
                cp16(st + OFF_BL + swoff[i], pbl + ke + i * 8);
            }
            CP_COMMIT();
            CP_WAIT2();
        } else if (c + 1 < nch) {
            CP_WAIT1();
        } else {
            CP_WAIT0();
        }
        __syncthreads();

        uint32_t sb = smb + stage * STAGE_BYTES;
#pragma unroll
        for (int kk = 0; kk < 4; kk++) {
            uint32_t brw = n_base + ((lane & 7) | ((lane >> 1) & 8));
            uint32_t bkb = kk * 32 + ((lane >> 3) & 1) * 16;
            uint32_t bh[8], bl[8];
#pragma unroll
            for (int np = 0; np < 2; np++) {
                uint32_t bo = (brw + np * 16) * 128 + bkb;
                uint32_t ad = sb + (bo ^ ((bo >> 3) & 0x70));
                ldmx4(bh + np * 4, ad + OFF_BH);
                ldmx4(bl + np * 4, ad + OFF_BL);
            }
            uint32_t arw = m_base + (lane & 15);
            uint32_t akb = kk * 32 + ((lane >> 4) & 1) * 16;
#pragma unroll
            for (int mt = 0; mt < 4; mt++) {
                uint32_t bo = (arw + mt * 16) * 128 + akb;
                uint32_t ad = sb + (bo ^ ((bo >> 3) & 0x70));
                uint32_t ah[4], al[4];
                ldmx4(ah, ad + OFF_AH);
                ldmx4(al, ad + OFF_AL);
#pragma unroll
                for (int nt = 0; nt < 4; nt++) {
                    int bi = (nt >> 1) * 4 + (nt & 1) * 2;
                    mma_bf16(acc[mt][nt], ah, bh[bi], bh[bi + 1]);
                    mma_bf16(acc[mt][nt], ah, bl[bi], bl[bi + 1]);
                    mma_bf16(acc[mt][nt], al, bh[bi], bh[bi + 1]);
                }
            }
        }
        __syncthreads();
        stage = (stage + 1 == 3) ? 0 : stage + 1;
    }

    // ---- epilogue: bias (+relu), direct stores
#pragma unroll
    for (int mt = 0; mt < 4; mt++) {
#pragma unroll
        for (int h2 = 0; h2 < 2; h2++) {
            int r = m0 + m_base + mt * 16 + h2 * 8 + (lane >> 2);
            if (r >= count) continue;
            int orow = scatter ? scatter[r] : r;
#pragma unroll
            for (int nt = 0; nt < 4; nt++) {
                int col = n0 + n_base + nt * 8 + (lane & 3) * 2;
                float v0 = acc[mt][nt][h2 * 2 + 0] + bias[col];
                float v1 = acc[mt][nt][h2 * 2 + 1] + bias[col + 1];
                if (relu) { v0 = fmaxf(v0, 0.f); v1 = fmaxf(v1, 0.f); }
                if (Cf) {
                    float2 o; o.x = v0; o.y = v1;
                    *(float2*)(Cf + (size_t)orow * ldCf + col) = o;
                }
                if (Chi) {
                    bf16 h0, l0, h1, l1;
                    split2(v0, h0, l0); split2(v1, h1, l1);
                    size_t co = (size_t)r * ldCb + col;
                    __nv_bfloat162 ph; ph.x = h0; ph.y = h1;
                    __nv_bfloat162 pl; pl.x = l0; pl.y = l1;
                    *(__nv_bfloat162*)(Chi + co) = ph;
                    *(__nv_bfloat162*)(Clo + co) = pl;
                }
            }
        }
    }
}

// ---------------- logits + argmax + inline compaction (unambiguous) ----------------
__global__ void logits_kernel(const float* __restrict__ W2, const float* __restrict__ b2) {
    int warp = (blockIdx.x * blockDim.x + threadIdx.x) >> 5;
    int lane = threadIdx.x & 31;
    if (warp >= T_TOK) return;
    const float* hrow = g_hmid + (size_t)warp * 512;
    float s0 = 0.f, s1 = 0.f, s2 = 0.f;
    for (int k = lane * 4; k < 512; k += 128) {
        float4 h = *(const float4*)(hrow + k);
        const float* w = W2 + k * 3;
        s0 += h.x * w[0] + h.y * w[3] + h.z * w[6] + h.w * w[9];
        s1 += h.x * w[1] + h.y * w[4] + h.z * w[7] + h.w * w[10];
        s2 += h.x * w[2] + h.y * w[5] + h.z * w[8] + h.w * w[11];
    }
#pragma unroll
    for (int o = 16; o > 0; o >>= 1) {
        s0 += __shfl_xor_sync(0xffffffffu, s0, o);
        s1 += __shfl_xor_sync(0xffffffffu, s1, o);
        s2 += __shfl_xor_sync(0xffffffffu, s2, o);
    }
    if (lane == 0) {
        s0 += b2[0]; s1 += b2[1]; s2 += b2[2];
        int sel = 0; float best = s0;
        if (s1 > best) { best = s1; sel = 1; }
        if (s2 > best) { best = s2; sel = 2; }
        float second = (sel == 0) ? fmaxf(s1, s2) : (sel == 1 ? fmaxf(s0, s2) : fmaxf(s0, s1));
        g_sel[warp] = sel;
        if (best - second < 1e-3f) {
            int p = atomicAdd(&g_cnt[2], 1);
            g_fix[p] = warp;
        } else {
            if (sel == 1)      { int p = atomicAdd(&g_cnt[0], 1); g_idx1[p] = warp; }
            else if (sel == 2) { int p = atomicAdd(&g_cnt[1], 1); g_idx2[p] = warp; }
        }
    }
}

// ---------------- fp32 exact recompute + compaction for ambiguous tokens ----------------
__global__ void fixup_kernel(const float* __restrict__ W1, const float* __restrict__ b1,
                             const float* __restrict__ W2, const float* __restrict__ b2) {
    __shared__ float hm[512];
    __shared__ float red[256];
    __shared__ float logit[3];
    int nfix = g_cnt[2];
    for (int i = blockIdx.x; i < nfix; i += gridDim.x) {
        int t = g_fix[i];
        const float* cr = g_combined + (size_t)t * HDIM;
        int j0 = threadIdx.x, j1 = threadIdx.x + 256;
        float a0 = b1[j0], a1 = b1[j1];
#pragma unroll 4
        for (int k = 0; k < HDIM; k++) {
            float c = __ldg(cr + k);
            a0 += c * W1[(size_t)k * 512 + j0];
            a1 += c * W1[(size_t)k * 512 + j1];
        }
        hm[j0] = fmaxf(a0, 0.f);
        hm[j1] = fmaxf(a1, 0.f);
        __syncthreads();
        for (int l = 0; l < 3; l++) {
            float p = hm[threadIdx.x] * W2[threadIdx.x * 3 + l] +
                      hm[threadIdx.x + 256] * W2[(threadIdx.x + 256) * 3 + l];
            red[threadIdx.x] = p; __syncthreads();
            for (int o = 128; o > 0; o >>= 1) {
                if (threadIdx.x < o) red[threadIdx.x] += red[threadIdx.x + o];
                __syncthreads();
            }
            if (threadIdx.x == 0) logit[l] = red[0] + b2[l];
            __syncthreads();
        }
        if (threadIdx.x == 0) {
            float s0 = logit[0], s1 = logit[1], s2 = logit[2];
            int sel = 0; float best = s0;
            if (s1 > best) { best = s1; sel = 1; }
            if (s2 > best) { sel = 2; }
            g_sel[t] = sel;
            if (sel == 1)      { int p = atomicAdd(&g_cnt[0], 1); g_idx1[p] = t; }
            else if (sel == 2) { int p = atomicAdd(&g_cnt[1], 1); g_idx2[p] = t; }
        }
        __syncthreads();
    }
}

__global__ void copy0_kernel(const float* __restrict__ x, float* __restrict__ out) {
    int t = blockIdx.x;
    if (g_sel[t] != 0) return;
    const float4* src = (const float4*)(x + (size_t)t * HDIM);
    float4* dst = (float4*)(out + (size_t)t * HDIM);
    for (int i = threadIdx.x; i < HDIM / 4; i += blockDim.x) dst[i] = src[i];
}

// ---------------- launch ----------------
extern "C" void kernel_launch(void* const* d_in, const int* in_sizes, int n_in,
                              void* d_out, int out_size) {
    const float* x      = (const float*)d_in[0];
    const float* freq   = (const float*)d_in[1];
    const float* imp    = (const float*)d_in[2];
    const float* sel_W1 = (const float*)d_in[3];
    const float* sel_b1 = (const float*)d_in[4];
    const float* sel_W2 = (const float*)d_in[5];
    const float* sel_b2 = (const float*)d_in[6];
    const float* c1_W   = (const float*)d_in[7];
    const float* c1_b   = (const float*)d_in[8];
    const float* f1_W   = (const float*)d_in[9];
    const float* f1_b   = (const float*)d_in[10];
    const float* d1_W   = (const float*)d_in[11];
    const float* d1_b   = (const float*)d_in[12];
    const float* c2_W   = (const float*)d_in[13];
    const float* c2_b   = (const float*)d_in[14];
    const float* f2_W   = (const float*)d_in[15];
    const float* f2_b   = (const float*)d_in[16];
    const float* d2_W   = (const float*)d_in[17];
    const float* d2_b   = (const float*)d_in[18];
    float* out = (float*)d_out;

    bf16 *xhi, *xlo, *chi, *clo, *mAhi, *mAlo, *mBhi, *mBlo, *whi, *wlo;
    float *hmid;
    int *idx1, *idx2, *cnt;
    cudaGetSymbolAddress((void**)&xhi, g_xhi);
    cudaGetSymbolAddress((void**)&xlo, g_xlo);
    cudaGetSymbolAddress((void**)&chi, g_chi);
    cudaGetSymbolAddress((void**)&clo, g_clo);
    cudaGetSymbolAddress((void**)&mAhi, g_mAhi);
    cudaGetSymbolAddress((void**)&mAlo, g_mAlo);
    cudaGetSymbolAddress((void**)&mBhi, g_mBhi);
    cudaGetSymbolAddress((void**)&mBlo, g_mBlo);
    cudaGetSymbolAddress((void**)&whi, g_whi);
    cudaGetSymbolAddress((void**)&wlo, g_wlo);
    cudaGetSymbolAddress((void**)&hmid, g_hmid);
    cudaGetSymbolAddress((void**)&idx1, g_idx1);
    cudaGetSymbolAddress((void**)&idx2, g_idx2);
    cudaGetSymbolAddress((void**)&cnt, g_cnt);

    cudaFuncSetAttribute(gemm_mma, cudaFuncAttributeMaxDynamicSharedMemorySize, GEMM_SMEM);

    // launch 0: prep (splits + counter init)
    prep_kernel<<<(T_TOK * HDIM / 4 + 255) / 256, 256>>>(x, freq, imp);

    // launch 1: merged weight transpose+split
    WAll wa;
    int ts = 0;
    auto setw = [&](int i, const float* src, int K, int N, unsigned off) {
        wa.d[i].src = src; wa.d[i].K = K; wa.d[i].N = N; wa.d[i].off = off;
        wa.d[i].tile_start = ts; ts += (N / 32) * (K / 32);
    };
    setw(0, sel_W1, 2048, 512,  O_SELW1);
    setw(1, c1_W,   2048, 1024, O_C1);
    setw(2, f1_W,   1024, 1024, O_F1);
    setw(3, d1_W,   1024, 2048, O_D1);
    setw(4, c2_W,   2048, 512,  O_C2);
    setw(5, f2_W,   512,  512,  O_F2);
    setw(6, d2_W,   512,  2048, O_D2);
    transpose_all_kernel<<<ts, dim3(32, 8)>>>(wa);

    const int MT = T_TOK / 128;   // 128 M-tiles (worst case)

    // launch 2: selector hidden (fp32 out, relu)
    gemm_mma<<<dim3(512 / 128, MT), 256, GEMM_SMEM>>>(
        chi, clo, 2048, whi + O_SELW1, wlo + O_SELW1, 2048, sel_b1, 2048,
        hmid, 512, nullptr, nullptr, 0, nullptr, nullptr, nullptr, T_TOK, 1);

    // launch 3: logits + argmax + compaction (unambiguous)
    logits_kernel<<<T_TOK / 8, 256>>>(sel_W2, sel_b2);
    // launch 4: exact fixup + compaction (ambiguous)
    fixup_kernel<<<64, 256>>>(sel_W1, sel_b1, sel_W2, sel_b2);

    // launch 5: expert-1 c1 GEMM  <-- ncu -s 5 -c 1 profiles THIS
    gemm_mma<<<dim3(1024 / 128, MT), 256, GEMM_SMEM>>>(
        xhi, xlo, 2048, whi + O_C1, wlo + O_C1, 2048, c1_b, 2048,
        nullptr, 0, mAhi, mAlo, 1024, idx1, nullptr, cnt + 0, 0, 0);

    // launch 6: identity tokens
    copy0_kernel<<<T_TOK, 128>>>(x, out);

    // remaining expert GEMMs
    gemm_mma<<<dim3(1024 / 128, MT), 256, GEMM_SMEM>>>(
        mAhi, mAlo, 1024, whi + O_F1, wlo + O_F1, 1024, f1_b, 1024,
        nullptr, 0, mBhi, mBlo, 1024, nullptr, nullptr, cnt + 0, 0, 0);
    gemm_mma<<<dim3(2048 / 128, MT), 256, GEMM_SMEM>>>(
        mBhi, mBlo, 1024, whi + O_D1, wlo + O_D1, 1024, d1_b, 1024,
        out, 2048, nullptr, nullptr, 0, nullptr, idx1, cnt + 0, 0, 0);

    gemm_mma<<<dim3(512 / 128, MT), 256, GEMM_SMEM>>>(
        xhi, xlo, 2048, whi + O_C2, wlo + O_C2, 2048, c2_b, 2048,
        nullptr, 0, mAhi, mAlo, 512, idx2, nullptr, cnt + 1, 0, 0);
    gemm_mma<<<dim3(512 / 128, MT), 256, GEMM_SMEM>>>(
        mAhi, mAlo, 512, whi + O_F2, wlo + O_F2, 512, f2_b, 512,
        nullptr, 0, mBhi, mBlo, 512, nullptr, nullptr, cnt + 1, 0, 0);
    gemm_mma<<<dim3(2048 / 128, MT), 256, GEMM_SMEM>>>(
        mBhi, mBlo, 512, whi + O_D2, wlo + O_D2, 512, d2_b, 512,
        out, 2048, nullptr, nullptr, 0, nullptr, idx2, cnt + 1, 0, 0);
}